// round 8
// baseline (speedup 1.0000x reference)
#include <cuda_runtime.h>
#include <cooperative_groups.h>
namespace cg = cooperative_groups;

#define Nn 20000
#define Ee 160000

// ---------------- scratch (device globals: allocation-free) ----------------
__device__ float g_h[Nn * 256];      // per node: [u][ h0, h1x, h1y, h1z ] interleaved
__device__ float g_sc[Nn * 320];     // [sc0(128) | sc1 as w*3+d (192)]
__device__ float g_s[Nn * 512];      // per node: [s0(128) | s1x(128) | s1y(128) | s1z(128)]
__device__ int   g_cnt[Nn];
__device__ int   g_cur[Nn];
__device__ int   g_off[Nn + 1];
__device__ int   g_eperm[Ee];
__device__ int   g_esrc[Ee];         // src node per dst-sorted edge
__device__ float g_hid[Ee * 8];      // silu(emb@Wm1) per dst-sorted edge
__device__ float g_eap[Ee * 4];      // edge_attrs per dst-sorted edge

__device__ __forceinline__ float silu_f(float x) { return x / (1.0f + __expf(-x)); }

extern __shared__ float smem_dyn[];

// ---------------- CSR build + edge prep: single cooperative kernel ----------------
__global__ void k_csr(const int* __restrict__ ei, const float* __restrict__ emb,
                      const float* __restrict__ ea, const float* __restrict__ Wm1) {
    cg::grid_group grid = cg::this_grid();
    __shared__ float wm1[64];
    int tid = blockIdx.x * blockDim.x + threadIdx.x;
    int nthr = gridDim.x * blockDim.x;
    if (threadIdx.x < 64) wm1[threadIdx.x] = Wm1[threadIdx.x];
    __syncthreads();

    for (int i = tid; i < Nn; i += nthr) { g_cnt[i] = 0; g_cur[i] = 0; }
    grid.sync();

    for (int e = tid; e < Ee; e += nthr) atomicAdd(&g_cnt[ei[Ee + e]], 1);
    grid.sync();

    if (blockIdx.x == 0) {
        __shared__ int sh[512];
        __shared__ int carry;
        int t = threadIdx.x;
        if (t == 0) carry = 0;
        __syncthreads();
        for (int base = 0; base < Nn; base += 512) {
            int v = (base + t < Nn) ? g_cnt[base + t] : 0;
            sh[t] = v;
            __syncthreads();
            for (int off = 1; off < 512; off <<= 1) {
                int x = (t >= off) ? sh[t - off] : 0;
                __syncthreads();
                sh[t] += x;
                __syncthreads();
            }
            if (base + t < Nn) g_off[base + t] = carry + sh[t] - v;  // exclusive
            __syncthreads();
            if (t == 0) carry += sh[511];
            __syncthreads();
        }
        if (t == 0) g_off[Nn] = carry;
    }
    grid.sync();

    for (int e = tid; e < Ee; e += nthr) {
        int dst = ei[Ee + e];
        int pos = g_off[dst] + atomicAdd(&g_cur[dst], 1);
        g_eperm[pos] = e;
    }
    grid.sync();

    const float inv_e = 0.35355339059327373f;   // 1/sqrt(8)
    for (int pos = tid; pos < Ee; pos += nthr) {
        int e = g_eperm[pos];
        g_esrc[pos] = ei[e];
        float4 e0 = *(const float4*)(emb + (size_t)e * 8);
        float4 e1 = *(const float4*)(emb + (size_t)e * 8 + 4);
        #pragma unroll
        for (int j = 0; j < 8; j++) {
            float a = e0.x * wm1[0 * 8 + j] + e0.y * wm1[1 * 8 + j]
                    + e0.z * wm1[2 * 8 + j] + e0.w * wm1[3 * 8 + j]
                    + e1.x * wm1[4 * 8 + j] + e1.y * wm1[5 * 8 + j]
                    + e1.z * wm1[6 * 8 + j] + e1.w * wm1[7 * 8 + j];
            g_hid[(size_t)pos * 8 + j] = silu_f(a * inv_e);
        }
        *(float4*)(g_eap + (size_t)pos * 4) = *(const float4*)(ea + (size_t)e * 4);
    }
}

// ---------------- h = lin1(node_feats), interleaved output layout ----------------
__global__ void k_h(const float* __restrict__ nf,
                    const float* __restrict__ W10, const float* __restrict__ W11) {
    __shared__ float w10[4096], w11[4096], xs[256], os[256];
    int t = threadIdx.x;
    for (int i = t; i < 4096; i += 256) { w10[i] = W10[i]; w11[i] = W11[i]; }
    __syncthreads();
    for (int n = blockIdx.x; n < Nn; n += gridDim.x) {
        xs[t] = nf[(size_t)n * 256 + t];
        __syncthreads();
        float acc = 0.f;
        if (t < 64) {
            #pragma unroll 8
            for (int k = 0; k < 64; k++) acc += xs[k] * w10[k * 64 + t];
            os[t * 4] = acc * 0.125f;
        } else {
            int i = t - 64, d = i >> 6, v = i & 63;
            #pragma unroll 8
            for (int k = 0; k < 64; k++) acc += xs[64 + k * 3 + d] * w11[k * 64 + v];
            os[v * 4 + 1 + d] = acc * 0.125f;
        }
        __syncthreads();
        g_h[(size_t)n * 256 + t] = os[t];
        __syncthreads();
    }
}

// ---------------- sc (skip connection): 512 thr, 16 warps/SM, warp x 2 nodes ----------
__global__ __launch_bounds__(512, 1)
void k_sc(const float* __restrict__ nf, const float* __restrict__ na,
          const float* __restrict__ Wsc0, const float* __restrict__ Wsc1) {
    float* wsc0 = smem_dyn;            // 32768 floats (128KB)
    float* wsc1 = wsc0 + 32768;        // 16384 floats (64KB)
    float* xsb  = wsc1 + 16384;        // 16 warps * 2 nodes * 256 floats (32KB)
    int t = threadIdx.x;               // 512 threads
    for (int i = t; i < 32768; i += 512) wsc0[i] = Wsc0[i];
    for (int i = t; i < 16384; i += 512) wsc1[i] = Wsc1[i];
    __syncthreads();
    int wid = t >> 5, lane = t & 31;
    float* xs = xsb + wid * 512;
    int warps = gridDim.x * 16;
    const float inv_sc = 0.0625f;      // 1/sqrt(64*4)
    const float4* w0 = (const float4*)wsc0;
    const float2* w1 = (const float2*)wsc1;

    for (int nb = (blockIdx.x * 16 + wid) * 2; nb < Nn; nb += warps * 2) {
        __syncwarp();
        #pragma unroll
        for (int nn = 0; nn < 2; nn++) {
            int n = nb + nn;
            if (n < Nn) {
                const float4* src = (const float4*)(nf + (size_t)n * 256);
                float4* dst = (float4*)(xs + nn * 256);
                dst[lane] = src[lane];
                dst[lane + 32] = src[lane + 32];
            }
        }
        float naz[2][4];
        #pragma unroll
        for (int nn = 0; nn < 2; nn++) {
            int n = (nb + nn < Nn) ? nb + nn : 0;
            float4 v = *(const float4*)(na + (size_t)n * 4);
            naz[nn][0] = v.x; naz[nn][1] = v.y; naz[nn][2] = v.z; naz[nn][3] = v.w;
        }
        __syncwarp();

        float4 acc0[2];
        #pragma unroll
        for (int nn = 0; nn < 2; nn++) acc0[nn] = make_float4(0, 0, 0, 0);
        #pragma unroll 4
        for (int u = 0; u < 64; u++) {
            float xv0 = xs[u], xv1 = xs[256 + u];
            #pragma unroll
            for (int z = 0; z < 4; z++) {
                float4 wv = w0[(u * 4 + z) * 32 + lane];
                float y0 = xv0 * naz[0][z];
                float y1 = xv1 * naz[1][z];
                acc0[0].x += y0 * wv.x; acc0[0].y += y0 * wv.y;
                acc0[0].z += y0 * wv.z; acc0[0].w += y0 * wv.w;
                acc0[1].x += y1 * wv.x; acc0[1].y += y1 * wv.y;
                acc0[1].z += y1 * wv.z; acc0[1].w += y1 * wv.w;
            }
        }

        float a1[2][2][3];
        #pragma unroll
        for (int nn = 0; nn < 2; nn++)
            #pragma unroll
            for (int p = 0; p < 2; p++)
                #pragma unroll
                for (int d = 0; d < 3; d++) a1[nn][p][d] = 0.f;
        #pragma unroll 4
        for (int u = 0; u < 64; u++) {
            float2 wz0 = w1[(u * 4 + 0) * 32 + lane];
            float2 wz1 = w1[(u * 4 + 1) * 32 + lane];
            float2 wz2 = w1[(u * 4 + 2) * 32 + lane];
            float2 wz3 = w1[(u * 4 + 3) * 32 + lane];
            #pragma unroll
            for (int nn = 0; nn < 2; nn++) {
                float wrx = naz[nn][0] * wz0.x + naz[nn][1] * wz1.x
                          + naz[nn][2] * wz2.x + naz[nn][3] * wz3.x;
                float wry = naz[nn][0] * wz0.y + naz[nn][1] * wz1.y
                          + naz[nn][2] * wz2.y + naz[nn][3] * wz3.y;
                float gx = xs[nn * 256 + 64 + u * 3];
                float gy = xs[nn * 256 + 64 + u * 3 + 1];
                float gz = xs[nn * 256 + 64 + u * 3 + 2];
                a1[nn][0][0] += wrx * gx; a1[nn][0][1] += wrx * gy; a1[nn][0][2] += wrx * gz;
                a1[nn][1][0] += wry * gx; a1[nn][1][1] += wry * gy; a1[nn][1][2] += wry * gz;
            }
        }

        #pragma unroll
        for (int nn = 0; nn < 2; nn++) {
            int n = nb + nn;
            if (n >= Nn) continue;
            float4 r0;
            r0.x = acc0[nn].x * inv_sc; r0.y = acc0[nn].y * inv_sc;
            r0.z = acc0[nn].z * inv_sc; r0.w = acc0[nn].w * inv_sc;
            ((float4*)(g_sc + (size_t)n * 320))[lane] = r0;
            float* o = g_sc + (size_t)n * 320 + 128 + lane * 6;
            o[0] = a1[nn][0][0] * inv_sc; o[1] = a1[nn][0][1] * inv_sc;
            o[2] = a1[nn][0][2] * inv_sc; o[3] = a1[nn][1][0] * inv_sc;
            o[4] = a1[nn][1][1] * inv_sc; o[5] = a1[nn][1][2] * inv_sc;
        }
    }
}

// ---------------- edge reduction: 32 warps/SM, warp-per-node, writes g_s ----------
__global__ __launch_bounds__(512, 2)
void k_edge(const float* __restrict__ Wm2) {
    __shared__ float wm2s[2048];     // [j][u][4] = (w1,w2,w3,w4)
    int t = threadIdx.x;
    for (int i = t; i < 2048; i += 512) {
        int j = i >> 8, r = i & 255, c = r >> 6, u = r & 63;
        wm2s[(j * 64 + u) * 4 + c] = Wm2[i];
    }
    __syncthreads();
    int wid = t >> 5, lane = t & 31;
    int warps = gridDim.x * 16;
    const float inv_e = 0.35355339059327373f;   // 1/sqrt(8)
    const float inv_n = 0.35355339059327373f;   // 1/sqrt(8)
    const float is3   = 0.5773502691896258f;    // 1/sqrt(3)
    const float4* wm2v = (const float4*)wm2s;
    const float4* hid4 = (const float4*)g_hid;
    const float4* eap4 = (const float4*)g_eap;

    for (int n = blockIdx.x * 16 + wid; n < Nn; n += warps) {
        int beg = g_off[n], end = g_off[n + 1];
        float s0a[2] = {0, 0}, s0b[2] = {0, 0};
        float s1a[2][3] = {{0, 0, 0}, {0, 0, 0}};
        float s1b[2][3] = {{0, 0, 0}, {0, 0, 0}};

        float4 hv0_n = {0,0,0,0}, hv1_n = {0,0,0,0}, ea_n = {0,0,0,0};
        float4 ha_n = {0,0,0,0}, hb_n = {0,0,0,0};
        if (beg < end) {
            int s0 = g_esrc[beg];
            hv0_n = hid4[(size_t)beg * 2]; hv1_n = hid4[(size_t)beg * 2 + 1];
            ea_n  = eap4[beg];
            const float4* hp = (const float4*)(g_h + (size_t)s0 * 256);
            ha_n = hp[lane]; hb_n = hp[lane + 32];
        }
        for (int i = beg; i < end; i++) {
            float4 hv0 = hv0_n, hv1 = hv1_n, eav = ea_n, ha = ha_n, hb = hb_n;
            if (i + 1 < end) {
                int s1 = g_esrc[i + 1];
                hv0_n = hid4[(size_t)(i + 1) * 2]; hv1_n = hid4[(size_t)(i + 1) * 2 + 1];
                ea_n  = eap4[i + 1];
                const float4* hp = (const float4*)(g_h + (size_t)s1 * 256);
                ha_n = hp[lane]; hb_n = hp[lane + 32];
            }
            float hid[8] = { hv0.x, hv0.y, hv0.z, hv0.w, hv1.x, hv1.y, hv1.z, hv1.w };
            #pragma unroll
            for (int p = 0; p < 2; p++) {
                int u = lane + p * 32;
                float4 hvv = (p == 0) ? ha : hb;   // (h0, h1x, h1y, h1z)
                float w1 = 0, w2 = 0, w3 = 0, w4 = 0;
                #pragma unroll
                for (int j = 0; j < 8; j++) {
                    float4 wv = wm2v[j * 64 + u];
                    float h = hid[j];
                    w1 += h * wv.x; w2 += h * wv.y; w3 += h * wv.z; w4 += h * wv.w;
                }
                w1 *= inv_e; w2 *= inv_e; w3 *= inv_e; w4 *= inv_e;
                float g0 = hvv.x, gx = hvv.y, gy = hvv.z, gz = hvv.w;
                s0a[p] += w1 * g0 * eav.x;
                s0b[p] += w4 * (gx * eav.y + gy * eav.z + gz * eav.w) * is3;
                float c = w2 * g0;
                s1a[p][0] += c * eav.y; s1a[p][1] += c * eav.z; s1a[p][2] += c * eav.w;
                float b = w3 * eav.x;
                s1b[p][0] += b * gx; s1b[p][1] += b * gy; s1b[p][2] += b * gz;
            }
        }
        // write s: [s0(128) | s1x(128) | s1y(128) | s1z(128)]
        float* sp = g_s + (size_t)n * 512;
        #pragma unroll
        for (int p = 0; p < 2; p++) {
            int u = lane + p * 32;
            sp[u]      = s0a[p] * inv_n;
            sp[64 + u] = s0b[p] * inv_n;
            #pragma unroll
            for (int d = 0; d < 3; d++) {
                sp[128 + d * 128 + u]      = s1a[p][d] * inv_n;
                sp[128 + d * 128 + 64 + u] = s1b[p][d] * inv_n;
            }
        }
    }
}

// ---------------- lin2 + skip + gate + output: dense, 32 warps/SM, NT=2 ----------
__global__ __launch_bounds__(512, 2)
void k_lin2(const float* __restrict__ nf, const float* __restrict__ Wl20,
            const float* __restrict__ Wl21, float* __restrict__ out) {
    float* wl20 = smem_dyn;          // 16384 floats
    float* wl21 = wl20 + 16384;      // 8192 floats  (total 96KB)
    int t = threadIdx.x;             // 512
    for (int i = t; i < 16384; i += 512) wl20[i] = Wl20[i];
    for (int i = t; i < 8192; i += 512) wl21[i] = Wl21[i];
    __syncthreads();

    int wid = t >> 5, lane = t & 31;
    const float inv2 = 0.08838834764831845f;   // 1/sqrt(128)
    int warps = gridDim.x * 16;
    const float4* wp = (const float4*)wl20;
    const float2* wq = (const float2*)wl21;

    for (int nb = (blockIdx.x * 16 + wid) * 2; nb < Nn; nb += warps * 2) {
        int n0 = nb, n1 = (nb + 1 < Nn) ? nb + 1 : nb;

        // ---- t0 = s0 @ Wl20 : weights shared across 2 nodes, s via float4 ----
        float4 t0[2] = { {0,0,0,0}, {0,0,0,0} };
        const float4* s0p0 = (const float4*)(g_s + (size_t)n0 * 512);
        const float4* s0p1 = (const float4*)(g_s + (size_t)n1 * 512);
        #pragma unroll 4
        for (int k4 = 0; k4 < 32; k4++) {
            float4 sv0 = s0p0[k4], sv1 = s0p1[k4];
            #pragma unroll
            for (int kk = 0; kk < 4; kk++) {
                float4 wv = wp[(k4 * 4 + kk) * 32 + lane];
                float a = ((const float*)&sv0)[kk];
                float b = ((const float*)&sv1)[kk];
                t0[0].x += a * wv.x; t0[0].y += a * wv.y;
                t0[0].z += a * wv.z; t0[0].w += a * wv.w;
                t0[1].x += b * wv.x; t0[1].y += b * wv.y;
                t0[1].z += b * wv.z; t0[1].w += b * wv.w;
            }
        }

        // ---- t1 per node (d-major s1, float4 over k) ----
        float t1[2][2][3];
        #pragma unroll 1
        for (int nn = 0; nn < 2; nn++) {
            int n = (nn == 0) ? n0 : n1;
            const float4* sx = (const float4*)(g_s + (size_t)n * 512 + 128);
            const float4* sy = (const float4*)(g_s + (size_t)n * 512 + 256);
            const float4* sz = (const float4*)(g_s + (size_t)n * 512 + 384);
            float a00 = 0, a01 = 0, a02 = 0, a10 = 0, a11 = 0, a12 = 0;
            #pragma unroll 4
            for (int k4 = 0; k4 < 32; k4++) {
                float4 vx = sx[k4], vy = sy[k4], vz = sz[k4];
                #pragma unroll
                for (int kk = 0; kk < 4; kk++) {
                    float2 wv = wq[(k4 * 4 + kk) * 32 + lane];
                    float xx = ((const float*)&vx)[kk];
                    float yy = ((const float*)&vy)[kk];
                    float zz = ((const float*)&vz)[kk];
                    a00 += wv.x * xx; a01 += wv.x * yy; a02 += wv.x * zz;
                    a10 += wv.y * xx; a11 += wv.y * yy; a12 += wv.y * zz;
                }
            }
            t1[nn][0][0] = a00; t1[nn][0][1] = a01; t1[nn][0][2] = a02;
            t1[nn][1][0] = a10; t1[nn][1][1] = a11; t1[nn][1][2] = a12;
        }

        // ---- output per node; gates via shuffle (no smem staging) ----
        #pragma unroll 1
        for (int nn = 0; nn < 2; nn++) {
            int n = nb + nn;
            if (n >= Nn) continue;
            float4 sc0 = ((const float4*)(g_sc + (size_t)n * 320))[lane];
            float4 tt;
            tt.x = t0[nn].x * inv2 + sc0.x; tt.y = t0[nn].y * inv2 + sc0.y;
            tt.z = t0[nn].z * inv2 + sc0.z; tt.w = t0[nn].w * inv2 + sc0.w;
            float4 sg;
            sg.x = silu_f(tt.x); sg.y = silu_f(tt.y);
            sg.z = silu_f(tt.z); sg.w = silu_f(tt.w);
            // gates: t0[64 + w] for w = 2*lane, 2*lane+1 lives at lane 16+(lane>>1)
            int srcl = 16 + (lane >> 1);
            float ga = __shfl_sync(0xffffffffu, sg.x, srcl);
            float gb = __shfl_sync(0xffffffffu, sg.y, srcl);
            float gc = __shfl_sync(0xffffffffu, sg.z, srcl);
            float gd = __shfl_sync(0xffffffffu, sg.w, srcl);
            float gate0 = (lane & 1) ? gc : ga;
            float gate1 = (lane & 1) ? gd : gb;
            // scalars
            if (lane < 16) {
                float4 nfv = ((const float4*)(nf + (size_t)n * 256))[lane];
                float4 ov;
                ov.x = nfv.x + sg.x; ov.y = nfv.y + sg.y;
                ov.z = nfv.z + sg.z; ov.w = nfv.w + sg.w;
                ((float4*)(out + (size_t)n * 256))[lane] = ov;
            }
            // vectors: w = 2*lane, 2*lane+1
            int w = lane * 2;
            const float* sc1 = g_sc + (size_t)n * 320 + 128;
            float* ob = out + (size_t)n * 256;
            const float* nb2 = nf + (size_t)n * 256;
            #pragma unroll
            for (int d = 0; d < 3; d++) {
                int c0 = 64 + w * 3 + d, c1 = 64 + (w + 1) * 3 + d;
                ob[c0] = nb2[c0] + gate0 * (t1[nn][0][d] * inv2 + sc1[w * 3 + d]);
                ob[c1] = nb2[c1] + gate1 * (t1[nn][1][d] * inv2 + sc1[(w + 1) * 3 + d]);
            }
        }
    }
}

// ---------------- host ----------------
extern "C" void kernel_launch(void* const* d_in, const int* in_sizes, int n_in,
                              void* d_out, int out_size) {
    const float* nf   = (const float*)d_in[0];
    const float* na   = (const float*)d_in[1];
    const float* ea   = (const float*)d_in[2];
    const float* emb  = (const float*)d_in[3];
    const float* W10  = (const float*)d_in[4];
    const float* W11  = (const float*)d_in[5];
    const float* Wm1  = (const float*)d_in[6];
    const float* Wm2  = (const float*)d_in[7];
    const float* Wl20 = (const float*)d_in[8];
    const float* Wl21 = (const float*)d_in[9];
    const float* Wsc0 = (const float*)d_in[10];
    const float* Wsc1 = (const float*)d_in[11];
    const int*   ei   = (const int*)d_in[12];
    float* out = (float*)d_out;

    cudaFuncSetAttribute(k_sc,   cudaFuncAttributeMaxDynamicSharedMemorySize, 229376);
    cudaFuncSetAttribute(k_lin2, cudaFuncAttributeMaxDynamicSharedMemorySize, 98304);

    // launch #1: CSR + edge prep (cooperative)
    void* csr_args[] = { (void*)&ei, (void*)&emb, (void*)&ea, (void*)&Wm1 };
    cudaLaunchCooperativeKernel((void*)k_csr, dim3(148), dim3(512), csr_args, 0, 0);
    // launch #2
    k_h<<<1024, 256>>>(nf, W10, W11);
    // launch #3
    k_sc<<<148, 512, 229376>>>(nf, na, Wsc0, Wsc1);
    // launch #4 (ncu capture lands here)
    k_edge<<<296, 512>>>(Wm2);
    // launch #5
    k_lin2<<<296, 512, 98304>>>(nf, Wl20, Wl21, out);
}

// round 9
// speedup vs baseline: 1.3564x; 1.3564x over previous
#include <cuda_runtime.h>
#include <cooperative_groups.h>
namespace cg = cooperative_groups;

#define Nn 20000
#define Ee 160000

// ---------------- scratch (device globals: allocation-free) ----------------
__device__ float g_h[Nn * 256];      // per node: [u][ h0, h1x, h1y, h1z ] interleaved
__device__ float g_sc[Nn * 320];     // [sc0(128) | sc1 as w*3+d (192)]
__device__ int   g_cnt[Nn];
__device__ int   g_cur[Nn];
__device__ int   g_off[Nn + 1];
__device__ int   g_esrc[Ee];         // src node per dst-sorted edge
__device__ float g_hid[Ee * 8];      // silu(emb@Wm1) per dst-sorted edge
__device__ float g_eap[Ee * 4];      // edge_attrs per dst-sorted edge

__device__ __forceinline__ float silu_f(float x) { return x / (1.0f + __expf(-x)); }

extern __shared__ float smem_dyn[];

// ---------------- CSR build + fused edge prep: cooperative kernel ----------------
__global__ void k_csr(const int* __restrict__ ei, const float* __restrict__ emb,
                      const float* __restrict__ ea, const float* __restrict__ Wm1) {
    cg::grid_group grid = cg::this_grid();
    __shared__ float wm1[64];
    int tid = blockIdx.x * blockDim.x + threadIdx.x;
    int nthr = gridDim.x * blockDim.x;
    if (threadIdx.x < 64) wm1[threadIdx.x] = Wm1[threadIdx.x];
    __syncthreads();

    // phase 0: zero
    for (int i = tid; i < Nn; i += nthr) { g_cnt[i] = 0; g_cur[i] = 0; }
    grid.sync();

    // phase 1: histogram
    for (int e = tid; e < Ee; e += nthr) atomicAdd(&g_cnt[ei[Ee + e]], 1);
    grid.sync();

    // phase 2: exclusive scan (block 0 only)
    if (blockIdx.x == 0) {
        __shared__ int sh[512];
        __shared__ int carry;
        int t = threadIdx.x;
        if (t == 0) carry = 0;
        __syncthreads();
        for (int base = 0; base < Nn; base += 512) {
            int v = (base + t < Nn) ? g_cnt[base + t] : 0;
            sh[t] = v;
            __syncthreads();
            for (int off = 1; off < 512; off <<= 1) {
                int x = (t >= off) ? sh[t - off] : 0;
                __syncthreads();
                sh[t] += x;
                __syncthreads();
            }
            if (base + t < Nn) g_off[base + t] = carry + sh[t] - v;  // exclusive
            __syncthreads();
            if (t == 0) carry += sh[511];
            __syncthreads();
        }
        if (t == 0) g_off[Nn] = carry;
    }
    grid.sync();

    // phase 3: scatter + edge prep fused (all reads SEQUENTIAL in e)
    const float inv_e = 0.35355339059327373f;   // 1/sqrt(8)
    for (int e = tid; e < Ee; e += nthr) {
        int src = ei[e];
        int dst = ei[Ee + e];
        int pos = g_off[dst] + atomicAdd(&g_cur[dst], 1);
        g_esrc[pos] = src;
        float4 e0 = *(const float4*)(emb + (size_t)e * 8);
        float4 e1 = *(const float4*)(emb + (size_t)e * 8 + 4);
        float4 h0, h1;
        float* hp = (float*)&h0;
        #pragma unroll
        for (int j = 0; j < 8; j++) {
            float a = e0.x * wm1[0 * 8 + j] + e0.y * wm1[1 * 8 + j]
                    + e0.z * wm1[2 * 8 + j] + e0.w * wm1[3 * 8 + j]
                    + e1.x * wm1[4 * 8 + j] + e1.y * wm1[5 * 8 + j]
                    + e1.z * wm1[6 * 8 + j] + e1.w * wm1[7 * 8 + j];
            ((float*)&h0)[0] = ((float*)&h0)[0];  // keep compiler happy
            if (j < 4) ((float*)&h0)[j] = silu_f(a * inv_e);
            else       ((float*)&h1)[j - 4] = silu_f(a * inv_e);
        }
        (void)hp;
        *(float4*)(g_hid + (size_t)pos * 8)     = h0;
        *(float4*)(g_hid + (size_t)pos * 8 + 4) = h1;
        *(float4*)(g_eap + (size_t)pos * 4) = *(const float4*)(ea + (size_t)e * 4);
    }
}

// ---------------- h = lin1(node_feats), interleaved output layout ----------------
__global__ void k_h(const float* __restrict__ nf,
                    const float* __restrict__ W10, const float* __restrict__ W11,
                    int base, int count) {
    __shared__ float w10[4096], w11[4096], xs[256], os[256];
    int t = threadIdx.x;
    for (int i = t; i < 4096; i += 256) { w10[i] = W10[i]; w11[i] = W11[i]; }
    __syncthreads();
    for (int n = base + blockIdx.x; n < base + count; n += gridDim.x) {
        xs[t] = nf[(size_t)n * 256 + t];
        __syncthreads();
        float acc = 0.f;
        if (t < 64) {
            #pragma unroll 8
            for (int k = 0; k < 64; k++) acc += xs[k] * w10[k * 64 + t];
            os[t * 4] = acc * 0.125f;
        } else {
            int i = t - 64, d = i >> 6, v = i & 63;
            #pragma unroll 8
            for (int k = 0; k < 64; k++) acc += xs[64 + k * 3 + d] * w11[k * 64 + v];
            os[v * 4 + 1 + d] = acc * 0.125f;
        }
        __syncthreads();
        g_h[(size_t)n * 256 + t] = os[t];
        __syncthreads();
    }
}

// ---- compile-time float4-pair component select (folds under full unroll) ----
__device__ __forceinline__ float xcomp(const float4& a, const float4& b, int e) {
    switch (e) {
        case 0: return a.x; case 1: return a.y; case 2: return a.z; case 3: return a.w;
        case 4: return b.x; case 5: return b.y; case 6: return b.z; default: return b.w;
    }
}

// ---------------- sc: 512 thr / 16 warps/SM, NT=4, x in registers via shfl ----------
__global__ __launch_bounds__(512, 1)
void k_sc(const float* __restrict__ nf, const float* __restrict__ na,
          const float* __restrict__ Wsc0, const float* __restrict__ Wsc1) {
    float* wsc0 = smem_dyn;            // 32768 floats (128KB), [u][z][w128]
    float* wsc1 = wsc0 + 32768;        // 16384 floats (64KB),  [u][z][w64]
    int t = threadIdx.x;               // 512 threads
    for (int i = t; i < 32768; i += 512) wsc0[i] = Wsc0[i];
    for (int i = t; i < 16384; i += 512) wsc1[i] = Wsc1[i];
    __syncthreads();
    int wid = t >> 5, lane = t & 31;
    int warps = gridDim.x * 16;
    const float inv_sc = 0.0625f;      // 1/sqrt(64*4)
    const float4* w0 = (const float4*)wsc0;
    const float2* w1 = (const float2*)wsc1;

    for (int nb = (blockIdx.x * 16 + wid) * 4; nb < Nn; nb += warps * 4) {
        // x in registers: lane holds x[lane*8 .. lane*8+7] per node
        float4 xa[4], xb[4];
        float naz[4][4];
        #pragma unroll
        for (int nn = 0; nn < 4; nn++) {
            int n = (nb + nn < Nn) ? nb + nn : Nn - 1;
            const float4* src = (const float4*)(nf + (size_t)n * 256);
            xa[nn] = src[lane * 2];
            xb[nn] = src[lane * 2 + 1];
            float4 v = *(const float4*)(na + (size_t)n * 4);
            naz[nn][0] = v.x; naz[nn][1] = v.y; naz[nn][2] = v.z; naz[nn][3] = v.w;
        }

        float4 acc0[4];
        float a1[4][2][3];
        #pragma unroll
        for (int nn = 0; nn < 4; nn++) {
            acc0[nn] = make_float4(0, 0, 0, 0);
            #pragma unroll
            for (int p = 0; p < 2; p++)
                #pragma unroll
                for (int d = 0; d < 3; d++) a1[nn][p][d] = 0.f;
        }

        #pragma unroll 1
        for (int ub = 0; ub < 8; ub++) {
            #pragma unroll
            for (int r = 0; r < 8; r++) {
                int u = ub * 8 + r;
                // ---- sc0: x0[u] lives in lane ub, component r ----
                float xv[4];
                #pragma unroll
                for (int nn = 0; nn < 4; nn++)
                    xv[nn] = __shfl_sync(0xffffffffu, xcomp(xa[nn], xb[nn], r), ub);
                #pragma unroll
                for (int z = 0; z < 4; z++) {
                    float4 wv = w0[(u * 4 + z) * 32 + lane];
                    #pragma unroll
                    for (int nn = 0; nn < 4; nn++) {
                        float y = xv[nn] * naz[nn][z];
                        acc0[nn].x += y * wv.x; acc0[nn].y += y * wv.y;
                        acc0[nn].z += y * wv.z; acc0[nn].w += y * wv.w;
                    }
                }
                // ---- sc1: x1[u][d] at flat idx 64+u*3+d ----
                float2 wz0 = w1[(u * 4 + 0) * 32 + lane];
                float2 wz1 = w1[(u * 4 + 1) * 32 + lane];
                float2 wz2 = w1[(u * 4 + 2) * 32 + lane];
                float2 wz3 = w1[(u * 4 + 3) * 32 + lane];
                float g[4][3];
                #pragma unroll
                for (int d = 0; d < 3; d++) {
                    const int q = 3 * r + d;          // compile-time
                    const int e1 = q & 7, c1 = q >> 3;
                    #pragma unroll
                    for (int nn = 0; nn < 4; nn++)
                        g[nn][d] = __shfl_sync(0xffffffffu,
                                               xcomp(xa[nn], xb[nn], e1),
                                               8 + 3 * ub + c1);
                }
                #pragma unroll
                for (int nn = 0; nn < 4; nn++) {
                    float wrx = naz[nn][0] * wz0.x + naz[nn][1] * wz1.x
                              + naz[nn][2] * wz2.x + naz[nn][3] * wz3.x;
                    float wry = naz[nn][0] * wz0.y + naz[nn][1] * wz1.y
                              + naz[nn][2] * wz2.y + naz[nn][3] * wz3.y;
                    a1[nn][0][0] += wrx * g[nn][0];
                    a1[nn][0][1] += wrx * g[nn][1];
                    a1[nn][0][2] += wrx * g[nn][2];
                    a1[nn][1][0] += wry * g[nn][0];
                    a1[nn][1][1] += wry * g[nn][1];
                    a1[nn][1][2] += wry * g[nn][2];
                }
            }
        }

        // stores
        #pragma unroll
        for (int nn = 0; nn < 4; nn++) {
            int n = nb + nn;
            if (n >= Nn) continue;
            float4 r0;
            r0.x = acc0[nn].x * inv_sc; r0.y = acc0[nn].y * inv_sc;
            r0.z = acc0[nn].z * inv_sc; r0.w = acc0[nn].w * inv_sc;
            ((float4*)(g_sc + (size_t)n * 320))[lane] = r0;
            float* o = g_sc + (size_t)n * 320 + 128 + lane * 6;
            o[0] = a1[nn][0][0] * inv_sc; o[1] = a1[nn][0][1] * inv_sc;
            o[2] = a1[nn][0][2] * inv_sc; o[3] = a1[nn][1][0] * inv_sc;
            o[4] = a1[nn][1][1] * inv_sc; o[5] = a1[nn][1][2] * inv_sc;
        }
    }
}

// ---------------- fused gather-reduce + lin2 + skip + gate + output ----------------
// round-7 proven config: 512 thr, Wm2 in registers, sequential edge streams (140us)
__global__ __launch_bounds__(512, 1)
void k_final(const float* __restrict__ nf,
             const float* __restrict__ Wm2, const float* __restrict__ Wl20,
             const float* __restrict__ Wl21, float* __restrict__ out) {
    float* wl20 = smem_dyn;          // 16384 floats
    float* wl21 = wl20 + 16384;      // 8192
    float* stg  = wl21 + 8192;       // 16 warps * 2 nodes * 512
    int t = threadIdx.x;             // 512
    for (int i = t; i < 16384; i += 512) wl20[i] = Wl20[i];
    for (int i = t; i < 8192; i += 512) wl21[i] = Wl21[i];
    __syncthreads();

    int wid = t >> 5, lane = t & 31;
    float* stw = stg + wid * 1024;   // 2 nodes * 512
    const float inv_e = 0.35355339059327373f;   // 1/sqrt(8)
    const float inv_n = 0.35355339059327373f;   // 1/sqrt(8)
    const float inv2  = 0.08838834764831845f;   // 1/sqrt(128)
    const float is3   = 0.5773502691896258f;    // 1/sqrt(3)
    int warps = gridDim.x * 16;

    float4 wr[2][8];
    #pragma unroll
    for (int p = 0; p < 2; p++) {
        int u = lane + p * 32;
        #pragma unroll
        for (int j = 0; j < 8; j++) {
            wr[p][j].x = Wm2[j * 256 + u];
            wr[p][j].y = Wm2[j * 256 + 64 + u];
            wr[p][j].z = Wm2[j * 256 + 128 + u];
            wr[p][j].w = Wm2[j * 256 + 192 + u];
        }
    }

    const float4* hid4 = (const float4*)g_hid;
    const float4* eap4 = (const float4*)g_eap;

    for (int nb = (blockIdx.x * 16 + wid) * 2; nb < Nn; nb += warps * 2) {
        __syncwarp();
        #pragma unroll 1
        for (int nn = 0; nn < 2; nn++) {
            int n = nb + nn;
            int beg = (n < Nn) ? g_off[n] : 0;
            int end = (n < Nn) ? g_off[n + 1] : 0;
            float s0a[2] = {0, 0}, s0b[2] = {0, 0};
            float s1a[2][3] = {{0, 0, 0}, {0, 0, 0}};
            float s1b[2][3] = {{0, 0, 0}, {0, 0, 0}};

            float4 hv0_n = {0,0,0,0}, hv1_n = {0,0,0,0}, ea_n = {0,0,0,0};
            float4 ha_n = {0,0,0,0}, hb_n = {0,0,0,0};
            if (beg < end) {
                int s0 = g_esrc[beg];
                hv0_n = hid4[(size_t)beg * 2]; hv1_n = hid4[(size_t)beg * 2 + 1];
                ea_n  = eap4[beg];
                const float4* hp = (const float4*)(g_h + (size_t)s0 * 256);
                ha_n = hp[lane]; hb_n = hp[lane + 32];
            }
            for (int i = beg; i < end; i++) {
                float4 hv0 = hv0_n, hv1 = hv1_n, eav = ea_n, ha = ha_n, hb = hb_n;
                if (i + 1 < end) {
                    int s1 = g_esrc[i + 1];
                    hv0_n = hid4[(size_t)(i + 1) * 2]; hv1_n = hid4[(size_t)(i + 1) * 2 + 1];
                    ea_n  = eap4[i + 1];
                    const float4* hp = (const float4*)(g_h + (size_t)s1 * 256);
                    ha_n = hp[lane]; hb_n = hp[lane + 32];
                }
                float hid[8] = { hv0.x, hv0.y, hv0.z, hv0.w, hv1.x, hv1.y, hv1.z, hv1.w };
                #pragma unroll
                for (int p = 0; p < 2; p++) {
                    float4 hvv = (p == 0) ? ha : hb;
                    float w1 = 0, w2 = 0, w3 = 0, w4 = 0;
                    #pragma unroll
                    for (int j = 0; j < 8; j++) {
                        float h = hid[j];
                        w1 += h * wr[p][j].x; w2 += h * wr[p][j].y;
                        w3 += h * wr[p][j].z; w4 += h * wr[p][j].w;
                    }
                    w1 *= inv_e; w2 *= inv_e; w3 *= inv_e; w4 *= inv_e;
                    float g0 = hvv.x, gx = hvv.y, gy = hvv.z, gz = hvv.w;
                    s0a[p] += w1 * g0 * eav.x;
                    s0b[p] += w4 * (gx * eav.y + gy * eav.z + gz * eav.w) * is3;
                    float c = w2 * g0;
                    s1a[p][0] += c * eav.y; s1a[p][1] += c * eav.z; s1a[p][2] += c * eav.w;
                    float b = w3 * eav.x;
                    s1b[p][0] += b * gx; s1b[p][1] += b * gy; s1b[p][2] += b * gz;
                }
            }
            float* st = stw + nn * 512;
            #pragma unroll
            for (int p = 0; p < 2; p++) {
                int u = lane + p * 32;
                st[u]      = s0a[p] * inv_n;
                st[64 + u] = s0b[p] * inv_n;
                #pragma unroll
                for (int d = 0; d < 3; d++) {
                    st[128 + u * 3 + d]        = s1a[p][d] * inv_n;
                    st[128 + (64 + u) * 3 + d] = s1b[p][d] * inv_n;
                }
            }
        }
        __syncwarp();

        float4 t0[2];
        #pragma unroll
        for (int nn = 0; nn < 2; nn++) t0[nn] = make_float4(0, 0, 0, 0);
        const float4* wp = (const float4*)wl20;
        #pragma unroll 4
        for (int k = 0; k < 128; k++) {
            float4 wv = wp[k * 32 + lane];
            #pragma unroll
            for (int nn = 0; nn < 2; nn++) {
                float s = stw[nn * 512 + k];
                t0[nn].x += s * wv.x; t0[nn].y += s * wv.y;
                t0[nn].z += s * wv.z; t0[nn].w += s * wv.w;
            }
        }
        float t1[2][2][3];
        #pragma unroll
        for (int nn = 0; nn < 2; nn++)
            #pragma unroll
            for (int p = 0; p < 2; p++)
                #pragma unroll
                for (int d = 0; d < 3; d++) t1[nn][p][d] = 0.f;
        const float2* wq = (const float2*)wl21;
        #pragma unroll 4
        for (int k = 0; k < 128; k++) {
            float2 wv = wq[k * 32 + lane];
            #pragma unroll
            for (int nn = 0; nn < 2; nn++) {
                const float* sb = stw + nn * 512 + 128 + k * 3;
                float y0 = sb[0], y1 = sb[1], y2 = sb[2];
                t1[nn][0][0] += wv.x * y0; t1[nn][0][1] += wv.x * y1; t1[nn][0][2] += wv.x * y2;
                t1[nn][1][0] += wv.y * y0; t1[nn][1][1] += wv.y * y1; t1[nn][1][2] += wv.y * y2;
            }
        }
        __syncwarp();

        #pragma unroll 1
        for (int nn = 0; nn < 2; nn++) {
            int n = nb + nn;
            if (n >= Nn) continue;
            float* st = stw + nn * 512;
            float4 sc0 = ((const float4*)(g_sc + (size_t)n * 320))[lane];
            float4 tt;
            tt.x = t0[nn].x * inv2 + sc0.x; tt.y = t0[nn].y * inv2 + sc0.y;
            tt.z = t0[nn].z * inv2 + sc0.z; tt.w = t0[nn].w * inv2 + sc0.w;
            int wbase = lane * 4;
            if (wbase < 64) {
                float4 nfv = ((const float4*)(nf + (size_t)n * 256))[lane];
                float4 ov;
                ov.x = nfv.x + silu_f(tt.x); ov.y = nfv.y + silu_f(tt.y);
                ov.z = nfv.z + silu_f(tt.z); ov.w = nfv.w + silu_f(tt.w);
                ((float4*)(out + (size_t)n * 256))[lane] = ov;
            } else {
                int u = wbase - 64;
                st[u]     = silu_f(tt.x);
                st[u + 1] = silu_f(tt.y);
                st[u + 2] = silu_f(tt.z);
                st[u + 3] = silu_f(tt.w);
            }
            __syncwarp();
            int w = lane * 2;
            const float* sc1 = g_sc + (size_t)n * 320 + 128;
            float gate0 = st[w], gate1 = st[w + 1];
            float* ob = out + (size_t)n * 256;
            const float* nb2 = nf + (size_t)n * 256;
            #pragma unroll
            for (int d = 0; d < 3; d++) {
                int c0 = 64 + w * 3 + d, c1 = 64 + (w + 1) * 3 + d;
                ob[c0] = nb2[c0] + gate0 * (t1[nn][0][d] * inv2 + sc1[w * 3 + d]);
                ob[c1] = nb2[c1] + gate1 * (t1[nn][1][d] * inv2 + sc1[(w + 1) * 3 + d]);
            }
            __syncwarp();
        }
    }
}

// ---------------- host ----------------
extern "C" void kernel_launch(void* const* d_in, const int* in_sizes, int n_in,
                              void* d_out, int out_size) {
    const float* nf   = (const float*)d_in[0];
    const float* na   = (const float*)d_in[1];
    const float* ea   = (const float*)d_in[2];
    const float* emb  = (const float*)d_in[3];
    const float* W10  = (const float*)d_in[4];
    const float* W11  = (const float*)d_in[5];
    const float* Wm1  = (const float*)d_in[6];
    const float* Wm2  = (const float*)d_in[7];
    const float* Wl20 = (const float*)d_in[8];
    const float* Wl21 = (const float*)d_in[9];
    const float* Wsc0 = (const float*)d_in[10];
    const float* Wsc1 = (const float*)d_in[11];
    const int*   ei   = (const int*)d_in[12];
    float* out = (float*)d_out;

    cudaFuncSetAttribute(k_sc,    cudaFuncAttributeMaxDynamicSharedMemorySize, 196608);
    cudaFuncSetAttribute(k_final, cudaFuncAttributeMaxDynamicSharedMemorySize, 163840);

    // launch #1: CSR + fused edge prep (cooperative)
    void* csr_args[] = { (void*)&ei, (void*)&emb, (void*)&ea, (void*)&Wm1 };
    cudaLaunchCooperativeKernel((void*)k_csr, dim3(148), dim3(512), csr_args, 0, 0);
    // launches #2, #3: k_h in two halves (positions the capture on k_sc)
    int b0 = 0, c0 = Nn / 2, b1 = Nn / 2, c1 = Nn - Nn / 2;
    k_h<<<512, 256>>>(nf, W10, W11, b0, c0);
    k_h<<<512, 256>>>(nf, W10, W11, b1, c1);
    // launch #4 (ncu capture): new shfl-based k_sc
    k_sc<<<148, 512, 196608>>>(nf, na, Wsc0, Wsc1);
    // launch #5
    k_final<<<148, 512, 163840>>>(nf, Wm2, Wl20, Wl21, out);
}

// round 10
// speedup vs baseline: 1.5692x; 1.1568x over previous
#include <cuda_runtime.h>
#include <cooperative_groups.h>
namespace cg = cooperative_groups;

#define Nn 20000
#define Ee 160000

// ---------------- scratch (device globals: allocation-free) ----------------
__device__ float g_h[Nn * 256];      // per node: [u][ h0, h1x, h1y, h1z ] interleaved
__device__ float g_sc[Nn * 320];     // [sc0(128) | sc1 as w*3+d (192)]
__device__ int   g_cnt[Nn];
__device__ int   g_cur[Nn];
__device__ int   g_off[Nn + 1];
__device__ int   g_bsum[256];
__device__ int   g_esrc[Ee];         // src node per dst-sorted edge
__device__ float g_hid[Ee * 8];      // silu(emb@Wm1) per dst-sorted edge
__device__ float g_eap[Ee * 4];      // edge_attrs per dst-sorted edge

__device__ __forceinline__ float silu_f(float x) { return x / (1.0f + __expf(-x)); }

extern __shared__ float smem_dyn[];

// ---------------- CSR build + fused edge prep: cooperative, parallel scan ----------
#define CSR_BLOCKS 148
#define CSR_CHUNK  ((Nn + CSR_BLOCKS - 1) / CSR_BLOCKS)   // 136

__global__ void k_csr(const int* __restrict__ ei, const float* __restrict__ emb,
                      const float* __restrict__ ea, const float* __restrict__ Wm1) {
    cg::grid_group grid = cg::this_grid();
    __shared__ float wm1[64];
    __shared__ int sh[512];
    int t = threadIdx.x;
    int tid = blockIdx.x * blockDim.x + t;
    int nthr = gridDim.x * blockDim.x;
    if (t < 64) wm1[t] = Wm1[t];
    __syncthreads();

    // phase 0: zero
    for (int i = tid; i < Nn; i += nthr) { g_cnt[i] = 0; g_cur[i] = 0; }
    grid.sync();

    // phase 1: histogram
    for (int e = tid; e < Ee; e += nthr) atomicAdd(&g_cnt[ei[Ee + e]], 1);
    grid.sync();

    // phase 2a: per-block scan of its chunk (local exclusive), record block total
    int base = blockIdx.x * CSR_CHUNK;
    {
        int v = (t < CSR_CHUNK && base + t < Nn) ? g_cnt[base + t] : 0;
        sh[t] = v;
        __syncthreads();
        for (int off = 1; off < 512; off <<= 1) {
            int x = (t >= off) ? sh[t - off] : 0;
            __syncthreads();
            sh[t] += x;
            __syncthreads();
        }
        if (t < CSR_CHUNK && base + t < Nn) g_off[base + t] = sh[t] - v;  // local excl
        if (t == 511) g_bsum[blockIdx.x] = sh[511];
        __syncthreads();
    }
    grid.sync();

    // phase 2b: block 0 scans the 148 block totals (exclusive), writes grand total
    if (blockIdx.x == 0) {
        int v = (t < CSR_BLOCKS) ? g_bsum[t] : 0;
        sh[t] = v;
        __syncthreads();
        for (int off = 1; off < 512; off <<= 1) {
            int x = (t >= off) ? sh[t - off] : 0;
            __syncthreads();
            sh[t] += x;
            __syncthreads();
        }
        if (t < CSR_BLOCKS) g_bsum[t] = sh[t] - v;  // exclusive
        if (t == CSR_BLOCKS - 1) g_off[Nn] = sh[t]; // grand total = Ee
    }
    grid.sync();

    // phase 2c: add block prefix
    {
        int pre = g_bsum[blockIdx.x];
        if (t < CSR_CHUNK && base + t < Nn) g_off[base + t] += pre;
    }
    grid.sync();

    // phase 3: scatter + edge prep fused (reads sequential in e, writes scattered)
    const float inv_e = 0.35355339059327373f;   // 1/sqrt(8)
    for (int e = tid; e < Ee; e += nthr) {
        int src = ei[e];
        int dst = ei[Ee + e];
        int pos = g_off[dst] + atomicAdd(&g_cur[dst], 1);
        g_esrc[pos] = src;
        float4 e0 = *(const float4*)(emb + (size_t)e * 8);
        float4 e1 = *(const float4*)(emb + (size_t)e * 8 + 4);
        float h[8];
        #pragma unroll
        for (int j = 0; j < 8; j++) {
            float a = e0.x * wm1[0 * 8 + j] + e0.y * wm1[1 * 8 + j]
                    + e0.z * wm1[2 * 8 + j] + e0.w * wm1[3 * 8 + j]
                    + e1.x * wm1[4 * 8 + j] + e1.y * wm1[5 * 8 + j]
                    + e1.z * wm1[6 * 8 + j] + e1.w * wm1[7 * 8 + j];
            h[j] = silu_f(a * inv_e);
        }
        *(float4*)(g_hid + (size_t)pos * 8)     = make_float4(h[0], h[1], h[2], h[3]);
        *(float4*)(g_hid + (size_t)pos * 8 + 4) = make_float4(h[4], h[5], h[6], h[7]);
        *(float4*)(g_eap + (size_t)pos * 4) = *(const float4*)(ea + (size_t)e * 4);
    }
}

// ---------------- h = lin1(node_feats), interleaved output layout ----------------
__global__ void k_h(const float* __restrict__ nf,
                    const float* __restrict__ W10, const float* __restrict__ W11) {
    __shared__ float w10[4096], w11[4096], xs[256], os[256];
    int t = threadIdx.x;
    for (int i = t; i < 4096; i += 256) { w10[i] = W10[i]; w11[i] = W11[i]; }
    __syncthreads();
    for (int n = blockIdx.x; n < Nn; n += gridDim.x) {
        xs[t] = nf[(size_t)n * 256 + t];
        __syncthreads();
        float acc = 0.f;
        if (t < 64) {
            #pragma unroll 8
            for (int k = 0; k < 64; k++) acc += xs[k] * w10[k * 64 + t];
            os[t * 4] = acc * 0.125f;
        } else {
            int i = t - 64, d = i >> 6, v = i & 63;
            #pragma unroll 8
            for (int k = 0; k < 64; k++) acc += xs[64 + k * 3 + d] * w11[k * 64 + v];
            os[v * 4 + 1 + d] = acc * 0.125f;
        }
        __syncthreads();
        g_h[(size_t)n * 256 + t] = os[t];
        __syncthreads();
    }
}

// ---------------- sc (skip connection): 512 thr, 16 warps/SM, warp x 2 nodes ----------
// round-5 proven config (96us)
__global__ __launch_bounds__(512, 1)
void k_sc(const float* __restrict__ nf, const float* __restrict__ na,
          const float* __restrict__ Wsc0, const float* __restrict__ Wsc1) {
    float* wsc0 = smem_dyn;            // 32768 floats (128KB)
    float* wsc1 = wsc0 + 32768;        // 16384 floats (64KB)
    float* xsb  = wsc1 + 16384;        // 16 warps * 2 nodes * 256 floats (32KB)
    int t = threadIdx.x;               // 512 threads
    for (int i = t; i < 32768; i += 512) wsc0[i] = Wsc0[i];
    for (int i = t; i < 16384; i += 512) wsc1[i] = Wsc1[i];
    __syncthreads();
    int wid = t >> 5, lane = t & 31;
    float* xs = xsb + wid * 512;
    int warps = gridDim.x * 16;
    const float inv_sc = 0.0625f;      // 1/sqrt(64*4)
    const float4* w0 = (const float4*)wsc0;
    const float2* w1 = (const float2*)wsc1;

    for (int nb = (blockIdx.x * 16 + wid) * 2; nb < Nn; nb += warps * 2) {
        __syncwarp();
        #pragma unroll
        for (int nn = 0; nn < 2; nn++) {
            int n = nb + nn;
            if (n < Nn) {
                const float4* src = (const float4*)(nf + (size_t)n * 256);
                float4* dst = (float4*)(xs + nn * 256);
                dst[lane] = src[lane];
                dst[lane + 32] = src[lane + 32];
            }
        }
        float naz[2][4];
        #pragma unroll
        for (int nn = 0; nn < 2; nn++) {
            int n = (nb + nn < Nn) ? nb + nn : 0;
            float4 v = *(const float4*)(na + (size_t)n * 4);
            naz[nn][0] = v.x; naz[nn][1] = v.y; naz[nn][2] = v.z; naz[nn][3] = v.w;
        }
        __syncwarp();

        float4 acc0[2];
        #pragma unroll
        for (int nn = 0; nn < 2; nn++) acc0[nn] = make_float4(0, 0, 0, 0);
        #pragma unroll 4
        for (int u = 0; u < 64; u++) {
            float xv0 = xs[u], xv1 = xs[256 + u];
            #pragma unroll
            for (int z = 0; z < 4; z++) {
                float4 wv = w0[(u * 4 + z) * 32 + lane];
                float y0 = xv0 * naz[0][z];
                float y1 = xv1 * naz[1][z];
                acc0[0].x += y0 * wv.x; acc0[0].y += y0 * wv.y;
                acc0[0].z += y0 * wv.z; acc0[0].w += y0 * wv.w;
                acc0[1].x += y1 * wv.x; acc0[1].y += y1 * wv.y;
                acc0[1].z += y1 * wv.z; acc0[1].w += y1 * wv.w;
            }
        }

        float a1[2][2][3];
        #pragma unroll
        for (int nn = 0; nn < 2; nn++)
            #pragma unroll
            for (int p = 0; p < 2; p++)
                #pragma unroll
                for (int d = 0; d < 3; d++) a1[nn][p][d] = 0.f;
        #pragma unroll 4
        for (int u = 0; u < 64; u++) {
            float2 wz0 = w1[(u * 4 + 0) * 32 + lane];
            float2 wz1 = w1[(u * 4 + 1) * 32 + lane];
            float2 wz2 = w1[(u * 4 + 2) * 32 + lane];
            float2 wz3 = w1[(u * 4 + 3) * 32 + lane];
            #pragma unroll
            for (int nn = 0; nn < 2; nn++) {
                float wrx = naz[nn][0] * wz0.x + naz[nn][1] * wz1.x
                          + naz[nn][2] * wz2.x + naz[nn][3] * wz3.x;
                float wry = naz[nn][0] * wz0.y + naz[nn][1] * wz1.y
                          + naz[nn][2] * wz2.y + naz[nn][3] * wz3.y;
                float gx = xs[nn * 256 + 64 + u * 3];
                float gy = xs[nn * 256 + 64 + u * 3 + 1];
                float gz = xs[nn * 256 + 64 + u * 3 + 2];
                a1[nn][0][0] += wrx * gx; a1[nn][0][1] += wrx * gy; a1[nn][0][2] += wrx * gz;
                a1[nn][1][0] += wry * gx; a1[nn][1][1] += wry * gy; a1[nn][1][2] += wry * gz;
            }
        }

        #pragma unroll
        for (int nn = 0; nn < 2; nn++) {
            int n = nb + nn;
            if (n >= Nn) continue;
            float4 r0;
            r0.x = acc0[nn].x * inv_sc; r0.y = acc0[nn].y * inv_sc;
            r0.z = acc0[nn].z * inv_sc; r0.w = acc0[nn].w * inv_sc;
            ((float4*)(g_sc + (size_t)n * 320))[lane] = r0;
            float* o = g_sc + (size_t)n * 320 + 128 + lane * 6;
            o[0] = a1[nn][0][0] * inv_sc; o[1] = a1[nn][0][1] * inv_sc;
            o[2] = a1[nn][0][2] * inv_sc; o[3] = a1[nn][1][0] * inv_sc;
            o[4] = a1[nn][1][1] * inv_sc; o[5] = a1[nn][1][2] * inv_sc;
        }
    }
}

// ---------------- fused gather-reduce + lin2 + skip + gate + output ----------------
// round-7 proven config: 512 thr, Wm2 in registers, sequential edge streams (140us)
__global__ __launch_bounds__(512, 1)
void k_final(const float* __restrict__ nf,
             const float* __restrict__ Wm2, const float* __restrict__ Wl20,
             const float* __restrict__ Wl21, float* __restrict__ out) {
    float* wl20 = smem_dyn;          // 16384 floats
    float* wl21 = wl20 + 16384;      // 8192
    float* stg  = wl21 + 8192;       // 16 warps * 2 nodes * 512
    int t = threadIdx.x;             // 512
    for (int i = t; i < 16384; i += 512) wl20[i] = Wl20[i];
    for (int i = t; i < 8192; i += 512) wl21[i] = Wl21[i];
    __syncthreads();

    int wid = t >> 5, lane = t & 31;
    float* stw = stg + wid * 1024;   // 2 nodes * 512
    const float inv_e = 0.35355339059327373f;   // 1/sqrt(8)
    const float inv_n = 0.35355339059327373f;   // 1/sqrt(8)
    const float inv2  = 0.08838834764831845f;   // 1/sqrt(128)
    const float is3   = 0.5773502691896258f;    // 1/sqrt(3)
    int warps = gridDim.x * 16;

    float4 wr[2][8];
    #pragma unroll
    for (int p = 0; p < 2; p++) {
        int u = lane + p * 32;
        #pragma unroll
        for (int j = 0; j < 8; j++) {
            wr[p][j].x = Wm2[j * 256 + u];
            wr[p][j].y = Wm2[j * 256 + 64 + u];
            wr[p][j].z = Wm2[j * 256 + 128 + u];
            wr[p][j].w = Wm2[j * 256 + 192 + u];
        }
    }

    const float4* hid4 = (const float4*)g_hid;
    const float4* eap4 = (const float4*)g_eap;

    for (int nb = (blockIdx.x * 16 + wid) * 2; nb < Nn; nb += warps * 2) {
        __syncwarp();
        #pragma unroll 1
        for (int nn = 0; nn < 2; nn++) {
            int n = nb + nn;
            int beg = (n < Nn) ? g_off[n] : 0;
            int end = (n < Nn) ? g_off[n + 1] : 0;
            float s0a[2] = {0, 0}, s0b[2] = {0, 0};
            float s1a[2][3] = {{0, 0, 0}, {0, 0, 0}};
            float s1b[2][3] = {{0, 0, 0}, {0, 0, 0}};

            float4 hv0_n = {0,0,0,0}, hv1_n = {0,0,0,0}, ea_n = {0,0,0,0};
            float4 ha_n = {0,0,0,0}, hb_n = {0,0,0,0};
            if (beg < end) {
                int s0 = g_esrc[beg];
                hv0_n = hid4[(size_t)beg * 2]; hv1_n = hid4[(size_t)beg * 2 + 1];
                ea_n  = eap4[beg];
                const float4* hp = (const float4*)(g_h + (size_t)s0 * 256);
                ha_n = hp[lane]; hb_n = hp[lane + 32];
            }
            for (int i = beg; i < end; i++) {
                float4 hv0 = hv0_n, hv1 = hv1_n, eav = ea_n, ha = ha_n, hb = hb_n;
                if (i + 1 < end) {
                    int s1 = g_esrc[i + 1];
                    hv0_n = hid4[(size_t)(i + 1) * 2]; hv1_n = hid4[(size_t)(i + 1) * 2 + 1];
                    ea_n  = eap4[i + 1];
                    const float4* hp = (const float4*)(g_h + (size_t)s1 * 256);
                    ha_n = hp[lane]; hb_n = hp[lane + 32];
                }
                float hid[8] = { hv0.x, hv0.y, hv0.z, hv0.w, hv1.x, hv1.y, hv1.z, hv1.w };
                #pragma unroll
                for (int p = 0; p < 2; p++) {
                    float4 hvv = (p == 0) ? ha : hb;
                    float w1 = 0, w2 = 0, w3 = 0, w4 = 0;
                    #pragma unroll
                    for (int j = 0; j < 8; j++) {
                        float h = hid[j];
                        w1 += h * wr[p][j].x; w2 += h * wr[p][j].y;
                        w3 += h * wr[p][j].z; w4 += h * wr[p][j].w;
                    }
                    w1 *= inv_e; w2 *= inv_e; w3 *= inv_e; w4 *= inv_e;
                    float g0 = hvv.x, gx = hvv.y, gy = hvv.z, gz = hvv.w;
                    s0a[p] += w1 * g0 * eav.x;
                    s0b[p] += w4 * (gx * eav.y + gy * eav.z + gz * eav.w) * is3;
                    float c = w2 * g0;
                    s1a[p][0] += c * eav.y; s1a[p][1] += c * eav.z; s1a[p][2] += c * eav.w;
                    float b = w3 * eav.x;
                    s1b[p][0] += b * gx; s1b[p][1] += b * gy; s1b[p][2] += b * gz;
                }
            }
            float* st = stw + nn * 512;
            #pragma unroll
            for (int p = 0; p < 2; p++) {
                int u = lane + p * 32;
                st[u]      = s0a[p] * inv_n;
                st[64 + u] = s0b[p] * inv_n;
                #pragma unroll
                for (int d = 0; d < 3; d++) {
                    st[128 + u * 3 + d]        = s1a[p][d] * inv_n;
                    st[128 + (64 + u) * 3 + d] = s1b[p][d] * inv_n;
                }
            }
        }
        __syncwarp();

        float4 t0[2];
        #pragma unroll
        for (int nn = 0; nn < 2; nn++) t0[nn] = make_float4(0, 0, 0, 0);
        const float4* wp = (const float4*)wl20;
        #pragma unroll 4
        for (int k = 0; k < 128; k++) {
            float4 wv = wp[k * 32 + lane];
            #pragma unroll
            for (int nn = 0; nn < 2; nn++) {
                float s = stw[nn * 512 + k];
                t0[nn].x += s * wv.x; t0[nn].y += s * wv.y;
                t0[nn].z += s * wv.z; t0[nn].w += s * wv.w;
            }
        }
        float t1[2][2][3];
        #pragma unroll
        for (int nn = 0; nn < 2; nn++)
            #pragma unroll
            for (int p = 0; p < 2; p++)
                #pragma unroll
                for (int d = 0; d < 3; d++) t1[nn][p][d] = 0.f;
        const float2* wq = (const float2*)wl21;
        #pragma unroll 4
        for (int k = 0; k < 128; k++) {
            float2 wv = wq[k * 32 + lane];
            #pragma unroll
            for (int nn = 0; nn < 2; nn++) {
                const float* sb = stw + nn * 512 + 128 + k * 3;
                float y0 = sb[0], y1 = sb[1], y2 = sb[2];
                t1[nn][0][0] += wv.x * y0; t1[nn][0][1] += wv.x * y1; t1[nn][0][2] += wv.x * y2;
                t1[nn][1][0] += wv.y * y0; t1[nn][1][1] += wv.y * y1; t1[nn][1][2] += wv.y * y2;
            }
        }
        __syncwarp();

        #pragma unroll 1
        for (int nn = 0; nn < 2; nn++) {
            int n = nb + nn;
            if (n >= Nn) continue;
            float* st = stw + nn * 512;
            float4 sc0 = ((const float4*)(g_sc + (size_t)n * 320))[lane];
            float4 tt;
            tt.x = t0[nn].x * inv2 + sc0.x; tt.y = t0[nn].y * inv2 + sc0.y;
            tt.z = t0[nn].z * inv2 + sc0.z; tt.w = t0[nn].w * inv2 + sc0.w;
            int wbase = lane * 4;
            if (wbase < 64) {
                float4 nfv = ((const float4*)(nf + (size_t)n * 256))[lane];
                float4 ov;
                ov.x = nfv.x + silu_f(tt.x); ov.y = nfv.y + silu_f(tt.y);
                ov.z = nfv.z + silu_f(tt.z); ov.w = nfv.w + silu_f(tt.w);
                ((float4*)(out + (size_t)n * 256))[lane] = ov;
            } else {
                int u = wbase - 64;
                st[u]     = silu_f(tt.x);
                st[u + 1] = silu_f(tt.y);
                st[u + 2] = silu_f(tt.z);
                st[u + 3] = silu_f(tt.w);
            }
            __syncwarp();
            int w = lane * 2;
            const float* sc1 = g_sc + (size_t)n * 320 + 128;
            float gate0 = st[w], gate1 = st[w + 1];
            float* ob = out + (size_t)n * 256;
            const float* nb2 = nf + (size_t)n * 256;
            #pragma unroll
            for (int d = 0; d < 3; d++) {
                int c0 = 64 + w * 3 + d, c1 = 64 + (w + 1) * 3 + d;
                ob[c0] = nb2[c0] + gate0 * (t1[nn][0][d] * inv2 + sc1[w * 3 + d]);
                ob[c1] = nb2[c1] + gate1 * (t1[nn][1][d] * inv2 + sc1[(w + 1) * 3 + d]);
            }
            __syncwarp();
        }
    }
}

// ---------------- host ----------------
extern "C" void kernel_launch(void* const* d_in, const int* in_sizes, int n_in,
                              void* d_out, int out_size) {
    const float* nf   = (const float*)d_in[0];
    const float* na   = (const float*)d_in[1];
    const float* ea   = (const float*)d_in[2];
    const float* emb  = (const float*)d_in[3];
    const float* W10  = (const float*)d_in[4];
    const float* W11  = (const float*)d_in[5];
    const float* Wm1  = (const float*)d_in[6];
    const float* Wm2  = (const float*)d_in[7];
    const float* Wl20 = (const float*)d_in[8];
    const float* Wl21 = (const float*)d_in[9];
    const float* Wsc0 = (const float*)d_in[10];
    const float* Wsc1 = (const float*)d_in[11];
    const int*   ei   = (const int*)d_in[12];
    float* out = (float*)d_out;

    cudaFuncSetAttribute(k_sc,    cudaFuncAttributeMaxDynamicSharedMemorySize, 229376);
    cudaFuncSetAttribute(k_final, cudaFuncAttributeMaxDynamicSharedMemorySize, 163840);

    // launch #1: CSR + fused edge prep (cooperative, parallel scan)
    void* csr_args[] = { (void*)&ei, (void*)&emb, (void*)&ea, (void*)&Wm1 };
    cudaLaunchCooperativeKernel((void*)k_csr, dim3(CSR_BLOCKS), dim3(512), csr_args, 0, 0);
    // launch #2
    k_h<<<1024, 256>>>(nf, W10, W11);
    // launch #3
    k_sc<<<148, 512, 229376>>>(nf, na, Wsc0, Wsc1);
    // launch #4 (ncu capture): k_final
    k_final<<<148, 512, 163840>>>(nf, Wm2, Wl20, Wl21, out);
}